// round 3
// baseline (speedup 1.0000x reference)
#include <cuda_runtime.h>

// ---------------------------------------------------------------------------
// PlainRNN: h_t = tanh(h_{t-1} @ W_eff + b_eff) with
//   W_eff = W_h2h + W_h2o @ W_i2h  (folds the x feedback into the recurrence)
// Outputs out[t] = h_t @ W_h2o + b_h2o computed as ONE batched GEMM at the end.
// ---------------------------------------------------------------------------

#define INPUT   128
#define HIDDEN  1024
#define OUTPUT  128
#define BATCH   256
#define TSTEPS  512

// Scratch (static device allocations are the sanctioned workaround).
// g_H[t] holds h_t for t = 1..511 (g_H[0] unused).
__device__ float g_H[TSTEPS][BATCH][HIDDEN];
__device__ float g_Weff[HIDDEN * HIDDEN];
__device__ float g_beff[HIDDEN];
__device__ float g_b1[HIDDEN];

// ---------------- packed fp32x2 helpers (Blackwell FFMA2 path) -------------
__device__ __forceinline__ unsigned long long pack2(float lo, float hi) {
    unsigned long long r;
    asm("mov.b64 %0, {%1, %2};" : "=l"(r) : "f"(lo), "f"(hi));
    return r;
}
__device__ __forceinline__ void unpack2(unsigned long long v, float& lo, float& hi) {
    asm("mov.b64 {%0, %1}, %2;" : "=f"(lo), "=f"(hi) : "l"(v));
}
__device__ __forceinline__ void ffma2(unsigned long long& d,
                                      unsigned long long a,
                                      unsigned long long b) {
    // d = a * b + d, elementwise on packed f32x2 (2 FMAs / instr).
    asm("fma.rn.f32x2 %0, %1, %2, %0;" : "+l"(d) : "l"(a), "l"(b));
}

// ---------------------------------------------------------------------------
// Tiled GEMM core: C[M,N] = act(A[M,K] @ B[K,N] + bias[N])
// Tile: BM=32, BN=64, BK=32. 256 threads; each thread computes 1x8 outputs
// as 4 packed f32x2 accumulators. A is staged transposed (k-major, padded)
// in smem so the inner a-broadcast is conflict-free.
// Grid: (N/64, M/32). Requires M%32==0, N%64==0, K%32==0.
// ---------------------------------------------------------------------------
template <bool TANH>
__device__ __forceinline__ void gemm_core(
    const float* __restrict__ A, int lda,
    const float* __restrict__ B, int ldb,
    const float* __restrict__ bias,
    float* __restrict__ C, int ldc,
    int K)
{
    __shared__ float As[32 * 33];   // [k][m], padded stride 33
    __shared__ float Bs[32 * 64];   // [k][n]

    const int tid = threadIdx.x;
    const int m   = tid >> 3;        // 0..31 output row within tile
    const int n   = (tid & 7) * 8;   // 0..56 output col base within tile

    const int rowBase = blockIdx.y * 32;
    const int colBase = blockIdx.x * 64;

    // A loader: thread reads float4 of 4 consecutive k at (a_m, a_k)
    const int a_m = tid >> 3;          // 0..31
    const int a_k = (tid & 7) * 4;     // 0,4,...,28
    // B loader: two float4 per thread
    const int b_k0 = tid >> 4;         // 0..15
    const int b_n4 = (tid & 15) * 4;   // 0,4,...,60

    unsigned long long acc[4];
#pragma unroll
    for (int p = 0; p < 4; ++p) acc[p] = 0ull;   // bit pattern 0 == (0.f, 0.f)

    for (int k0 = 0; k0 < K; k0 += 32) {
        // stage A tile transposed
        float4 av = *(const float4*)&A[(size_t)(rowBase + a_m) * lda + k0 + a_k];
        As[(a_k + 0) * 33 + a_m] = av.x;
        As[(a_k + 1) * 33 + a_m] = av.y;
        As[(a_k + 2) * 33 + a_m] = av.z;
        As[(a_k + 3) * 33 + a_m] = av.w;
        // stage B tile
#pragma unroll
        for (int r = 0; r < 2; ++r) {
            int bk = b_k0 + r * 16;
            float4 bv = *(const float4*)&B[(size_t)(k0 + bk) * ldb + colBase + b_n4];
            *(float4*)&Bs[bk * 64 + b_n4] = bv;
        }
        __syncthreads();

#pragma unroll
        for (int kk = 0; kk < 32; ++kk) {
            float a = As[kk * 33 + m];
            unsigned long long a2 = pack2(a, a);
            ulonglong2 bv0 = *(const ulonglong2*)&Bs[kk * 64 + n];
            ulonglong2 bv1 = *(const ulonglong2*)&Bs[kk * 64 + n + 4];
            ffma2(acc[0], a2, bv0.x);
            ffma2(acc[1], a2, bv0.y);
            ffma2(acc[2], a2, bv1.x);
            ffma2(acc[3], a2, bv1.y);
        }
        __syncthreads();
    }

    // epilogue: bias + optional tanh, vectorized store
    float o[8];
#pragma unroll
    for (int p = 0; p < 4; ++p) unpack2(acc[p], o[2 * p], o[2 * p + 1]);
#pragma unroll
    for (int q = 0; q < 8; ++q) {
        float c = o[q] + bias[colBase + n + q];
        o[q] = TANH ? tanhf(c) : c;
    }
    float* cp = &C[(size_t)(rowBase + m) * ldc + colBase + n];
    *(float4*)cp       = make_float4(o[0], o[1], o[2], o[3]);
    *(float4*)(cp + 4) = make_float4(o[4], o[5], o[6], o[7]);
}

// ---------------------------- wrappers -------------------------------------

// h_1 = tanh(x_0 @ W_i2h + b_i2h + b_h2h)       grid (16, 8)
__global__ void rnn_first(const float* __restrict__ x0,
                          const float* __restrict__ Wi2h) {
    gemm_core<true>(x0, INPUT, Wi2h, HIDDEN, g_b1,
                    &g_H[1][0][0], HIDDEN, INPUT);
}

// h_t = tanh(h_{t-1} @ W_eff + b_eff)           grid (16, 8)
__global__ void rnn_step(int t) {
    gemm_core<true>(&g_H[t - 1][0][0], HIDDEN, g_Weff, HIDDEN, g_beff,
                    &g_H[t][0][0], HIDDEN, HIDDEN);
}

// out[t] = h_t @ W_h2o + b_h2o for t=1..511     grid (2, 4088)
__global__ void out_proj(const float* __restrict__ Wh2o,
                         const float* __restrict__ bh2o,
                         float* __restrict__ out) {
    gemm_core<false>(&g_H[1][0][0], HIDDEN, Wh2o, OUTPUT, bh2o,
                     out + BATCH * OUTPUT, OUTPUT, HIDDEN);
}

// ---------------------------- prep kernels ---------------------------------

// W_eff[k][j] = W_h2h[k][j] + sum_i W_h2o[k][i] * W_i2h[i][j]
__global__ void prep_weff(const float* __restrict__ Wh2h,
                          const float* __restrict__ Wh2o,
                          const float* __restrict__ Wi2h) {
    int idx = blockIdx.x * blockDim.x + threadIdx.x;   // 1024*1024 threads
    int k = idx >> 10;
    int j = idx & 1023;
    float s = Wh2h[idx];
    const float* wo = &Wh2o[k * OUTPUT];
#pragma unroll 8
    for (int i = 0; i < OUTPUT; ++i)
        s += wo[i] * Wi2h[i * HIDDEN + j];
    g_Weff[idx] = s;
}

// b_eff[j] = b_i2h[j]+b_h2h[j] + sum_i b_h2o[i]*W_i2h[i][j];  b1 = b_i2h+b_h2h
__global__ void prep_bias(const float* __restrict__ bi2h,
                          const float* __restrict__ bh2h,
                          const float* __restrict__ bh2o,
                          const float* __restrict__ Wi2h) {
    int j = blockIdx.x * blockDim.x + threadIdx.x;
    if (j >= HIDDEN) return;
    float base = bi2h[j] + bh2h[j];
    g_b1[j] = base;
    float s = base;
#pragma unroll 8
    for (int i = 0; i < OUTPUT; ++i)
        s += bh2o[i] * Wi2h[i * HIDDEN + j];
    g_beff[j] = s;
}

// out[0] = x_0
__global__ void copy_x0(const float* __restrict__ x0, float* __restrict__ out) {
    int i = blockIdx.x * blockDim.x + threadIdx.x;
    if (i < BATCH * OUTPUT) out[i] = x0[i];
}

// ---------------------------- launcher -------------------------------------

extern "C" void kernel_launch(void* const* d_in, const int* in_sizes, int n_in,
                              void* d_out, int out_size) {
    const float* x0   = (const float*)d_in[0];
    const float* Wi2h = (const float*)d_in[1];
    const float* bi2h = (const float*)d_in[2];
    const float* Wh2h = (const float*)d_in[3];
    const float* bh2h = (const float*)d_in[4];
    const float* Wh2o = (const float*)d_in[5];
    const float* bh2o = (const float*)d_in[6];
    float* out = (float*)d_out;

    prep_weff<<<(HIDDEN * HIDDEN) / 256, 256>>>(Wh2h, Wh2o, Wi2h);
    prep_bias<<<(HIDDEN + 255) / 256, 256>>>(bi2h, bh2h, bh2o, Wi2h);
    copy_x0<<<(BATCH * OUTPUT + 255) / 256, 256>>>(x0, out);

    rnn_first<<<dim3(HIDDEN / 64, BATCH / 32), 256>>>(x0, Wi2h);
    for (int t = 2; t < TSTEPS; ++t)
        rnn_step<<<dim3(HIDDEN / 64, BATCH / 32), 256>>>(t);

    out_proj<<<dim3(OUTPUT / 64, ((TSTEPS - 1) * BATCH) / 32), 256>>>(Wh2o, bh2o, out);
}

// round 4
// speedup vs baseline: 2.5685x; 2.5685x over previous
#include <cuda_runtime.h>

// ---------------------------------------------------------------------------
// PlainRNN: h_t = tanh(h_{t-1} @ W_eff + b_eff) with
//   W_eff = W_h2h + W_h2o @ W_i2h  (x feedback folded into the recurrence)
// out[t] = h_t @ W_h2o + b_h2o done as ONE big batched GEMM at the end.
//
// GEMM core: 32x64 CTA tile, BK=16, 256 threads, 2x4 per-thread tile,
// A staged in smem as pre-duplicated packed f32x2, double-buffered smem,
// packed FFMA2 (fma.rn.f32x2) accumulators.
// ---------------------------------------------------------------------------

#define INPUT   128
#define HIDDEN  1024
#define OUTPUT  128
#define BATCH   256
#define TSTEPS  512

__device__ float g_H[TSTEPS][BATCH][HIDDEN];   // h_t for t=1..511
__device__ float g_Weff[HIDDEN * HIDDEN];
__device__ float g_beff[HIDDEN];
__device__ float g_b1[HIDDEN];

// ---------------- packed fp32x2 helpers ------------------------------------
__device__ __forceinline__ unsigned long long pack2(float lo, float hi) {
    unsigned long long r;
    asm("mov.b64 %0, {%1, %2};" : "=l"(r) : "f"(lo), "f"(hi));
    return r;
}
__device__ __forceinline__ void unpack2(unsigned long long v, float& lo, float& hi) {
    asm("mov.b64 {%0, %1}, %2;" : "=f"(lo), "=f"(hi) : "l"(v));
}
__device__ __forceinline__ void ffma2(unsigned long long& d,
                                      unsigned long long a,
                                      unsigned long long b) {
    asm("fma.rn.f32x2 %0, %1, %2, %0;" : "+l"(d) : "l"(a), "l"(b));
}

// ---------------------------------------------------------------------------
// C[M,N] = act(A[M,K] @ B[K,N] + bias[N])
// Grid: (N/64, M/32), 256 threads. Requires K%16==0, lda/ldb/ldc%4==0.
// ---------------------------------------------------------------------------
template <bool TANH>
__device__ __forceinline__ void gemm2(
    const float* __restrict__ A, int lda,
    const float* __restrict__ B, int ldb,
    const float* __restrict__ bias,
    float* __restrict__ C, int ldc,
    int K)
{
    // A duplicated as packed pairs: Asd[k][m] = (A, A). Row stride 34 keeps
    // 16B alignment for ulonglong2 reads (34*8 = 272 ≡ 0 mod 16).
    __shared__ unsigned long long Asd[2][16][34];
    __shared__ float Bs[2][16][68];   // 68*4 = 272, 16B-aligned rows

    const int tid = threadIdx.x;
    const int tx  = tid & 15;          // col group: 4 cols
    const int ty  = tid >> 4;          // row group: 2 rows
    const int rowBase = blockIdx.y * 32;
    const int colBase = blockIdx.x * 64;

    // loaders
    const int am = tid >> 3;           // 0..31
    const int ak = (tid & 7) * 2;      // 0..14
    const int bk = tid >> 4;           // 0..15
    const int bn = (tid & 15) * 4;     // 0..60

    const float* Aptr = &A[(size_t)(rowBase + am) * lda + ak];
    const float* Bptr = &B[(size_t)bk * ldb + colBase + bn];

    unsigned long long acc[2][2];
    acc[0][0] = acc[0][1] = acc[1][0] = acc[1][1] = 0ull;

    float2 rA = *(const float2*)Aptr;
    float4 rB = *(const float4*)Bptr;

    const int nT = K >> 4;
    for (int t = 0; t < nT; ++t) {
        const int buf = t & 1;
        Asd[buf][ak][am]     = pack2(rA.x, rA.x);
        Asd[buf][ak + 1][am] = pack2(rA.y, rA.y);
        *(float4*)&Bs[buf][bk][bn] = rB;
        __syncthreads();
        if (t + 1 < nT) {
            rA = *(const float2*)(Aptr + (t + 1) * 16);
            rB = *(const float4*)(Bptr + (size_t)(t + 1) * 16 * ldb);
        }
#pragma unroll
        for (int kk = 0; kk < 16; ++kk) {
            ulonglong2 ap = *(const ulonglong2*)&Asd[buf][kk][2 * ty];
            ulonglong2 bp = *(const ulonglong2*)&Bs[buf][kk][4 * tx];
            ffma2(acc[0][0], ap.x, bp.x);
            ffma2(acc[0][1], ap.x, bp.y);
            ffma2(acc[1][0], ap.y, bp.x);
            ffma2(acc[1][1], ap.y, bp.y);
        }
        // one sync per tile is sufficient: store(t+1) targets buf^1, whose
        // last reader finished compute(t-1), which precedes sync(t).
    }

    // epilogue
    float4 bv = *(const float4*)&bias[colBase + 4 * tx];
    float o[2][4];
#pragma unroll
    for (int r = 0; r < 2; ++r) {
        unpack2(acc[r][0], o[r][0], o[r][1]);
        unpack2(acc[r][1], o[r][2], o[r][3]);
        o[r][0] += bv.x; o[r][1] += bv.y; o[r][2] += bv.z; o[r][3] += bv.w;
        if (TANH) {
#pragma unroll
            for (int c = 0; c < 4; ++c) o[r][c] = tanhf(o[r][c]);
        }
        float* cp = &C[(size_t)(rowBase + 2 * ty + r) * ldc + colBase + 4 * tx];
        *(float4*)cp = make_float4(o[r][0], o[r][1], o[r][2], o[r][3]);
    }
}

// ---------------------------- wrappers -------------------------------------

// h_1 = tanh(x_0 @ W_i2h + b_i2h + b_h2h)           grid (16, 8)
__global__ void rnn_first(const float* __restrict__ x0,
                          const float* __restrict__ Wi2h) {
    gemm2<true>(x0, INPUT, Wi2h, HIDDEN, g_b1, &g_H[1][0][0], HIDDEN, INPUT);
}

// h_t = tanh(h_{t-1} @ W_eff + b_eff)               grid (16, 8)
__global__ void rnn_step(int t) {
    gemm2<true>(&g_H[t - 1][0][0], HIDDEN, g_Weff, HIDDEN, g_beff,
                &g_H[t][0][0], HIDDEN, HIDDEN);
}

// out[t] = h_t @ W_h2o + b_h2o for t=1..511         grid (2, 4088)
__global__ void out_proj(const float* __restrict__ Wh2o,
                         const float* __restrict__ bh2o,
                         float* __restrict__ out) {
    gemm2<false>(&g_H[1][0][0], HIDDEN, Wh2o, OUTPUT, bh2o,
                 out + BATCH * OUTPUT, OUTPUT, HIDDEN);
}

// ---------------------------- prep kernels ---------------------------------

// W_eff[k][j] = W_h2h[k][j] + sum_i W_h2o[k][i] * W_i2h[i][j]
__global__ void prep_weff(const float* __restrict__ Wh2h,
                          const float* __restrict__ Wh2o,
                          const float* __restrict__ Wi2h) {
    int idx = blockIdx.x * blockDim.x + threadIdx.x;
    int k = idx >> 10;
    int j = idx & 1023;
    float s = Wh2h[idx];
    const float* wo = &Wh2o[k * OUTPUT];
#pragma unroll 8
    for (int i = 0; i < OUTPUT; ++i)
        s += wo[i] * Wi2h[i * HIDDEN + j];
    g_Weff[idx] = s;
}

// b_eff[j] = b_i2h[j]+b_h2h[j] + sum_i b_h2o[i]*W_i2h[i][j];  b1 = b_i2h+b_h2h
__global__ void prep_bias(const float* __restrict__ bi2h,
                          const float* __restrict__ bh2h,
                          const float* __restrict__ bh2o,
                          const float* __restrict__ Wi2h) {
    int j = blockIdx.x * blockDim.x + threadIdx.x;
    if (j >= HIDDEN) return;
    float base = bi2h[j] + bh2h[j];
    g_b1[j] = base;
    float s = base;
#pragma unroll 8
    for (int i = 0; i < OUTPUT; ++i)
        s += bh2o[i] * Wi2h[i * HIDDEN + j];
    g_beff[j] = s;
}

// out[0] = x_0
__global__ void copy_x0(const float* __restrict__ x0, float* __restrict__ out) {
    int i = blockIdx.x * blockDim.x + threadIdx.x;
    if (i < BATCH * OUTPUT) out[i] = x0[i];
}

// ---------------------------- launcher -------------------------------------

extern "C" void kernel_launch(void* const* d_in, const int* in_sizes, int n_in,
                              void* d_out, int out_size) {
    const float* x0   = (const float*)d_in[0];
    const float* Wi2h = (const float*)d_in[1];
    const float* bi2h = (const float*)d_in[2];
    const float* Wh2h = (const float*)d_in[3];
    const float* bh2h = (const float*)d_in[4];
    const float* Wh2o = (const float*)d_in[5];
    const float* bh2o = (const float*)d_in[6];
    float* out = (float*)d_out;

    prep_weff<<<(HIDDEN * HIDDEN) / 256, 256>>>(Wh2h, Wh2o, Wi2h);
    prep_bias<<<(HIDDEN + 255) / 256, 256>>>(bi2h, bh2h, bh2o, Wi2h);
    copy_x0<<<(BATCH * OUTPUT + 255) / 256, 256>>>(x0, out);

    rnn_first<<<dim3(HIDDEN / 64, BATCH / 32), 256>>>(x0, Wi2h);
    for (int t = 2; t < TSTEPS; ++t)
        rnn_step<<<dim3(HIDDEN / 64, BATCH / 32), 256>>>(t);

    out_proj<<<dim3(OUTPUT / 64, ((TSTEPS - 1) * BATCH) / 32), 256>>>(Wh2o, bh2o, out);
}